// round 12
// baseline (speedup 1.0000x reference)
#include <cuda_runtime.h>
#include <cuda_bf16.h>
#include <mma.h>
#include <math.h>
#include <stdint.h>

using namespace nvcuda;

// ---------------------------------------------------------------------------
// QuanvolutionClassifier (sm_103a, HMMA path), FUSED:
//   prep  : split W1 (k-major, NO transpose) -> bf16 hi/lo [KP][128]
//   fused : per CTA, quantum circuits computed in-pipeline feeding A smem
//           slots; wmma bf16 split GEMM (AhBh+AhBl+AlBh, fp32 acc);
//           2 intra-CTA split-K groups; triple-buffered A(STS)/B(cp.async);
//           fused bias/relu + 128->10 GEMM + log_softmax.
// ---------------------------------------------------------------------------

#define MAX_B 4096
#define KP    832           // 784 padded (26*32)
#define HCHK  13            // chunks of 32 per K-group

__device__ __align__(16) __nv_bfloat16 g_w1h[KP * 128];   // zero-init padding
__device__ __align__(16) __nv_bfloat16 g_w1l[KP * 128];

// ========================= helpers =========================================
__device__ __forceinline__ uint32_t smem_u32(const void* p) {
    uint32_t a;
    asm("{ .reg .u64 t; cvta.to.shared.u64 t, %1; cvt.u32.u64 %0, t; }"
        : "=r"(a) : "l"(p));
    return a;
}
__device__ __forceinline__ void cp16(uint32_t dst, const void* src) {
    asm volatile("cp.async.cg.shared.global [%0], [%1], 16;"
                 :: "r"(dst), "l"(src) : "memory");
}
#define CP_COMMIT() asm volatile("cp.async.commit_group;" ::: "memory")
template <int N> __device__ __forceinline__ void cp_wait() {
    asm volatile("cp.async.wait_group %0;" :: "n"(N) : "memory");
}
__device__ __forceinline__ void gbar(int id) {
    asm volatile("bar.sync %0, 256;" :: "r"(id) : "memory");
}

// 4-qubit circuit: 4 pixel angles -> 4 PauliZ expectations
__device__ __forceinline__ void run_circuit(float x0, float x1, float x2, float x3,
                                            const float2* sTrig, float o[4]) {
    float c[4], s[4];
    __sincosf(0.5f * x0, &s[0], &c[0]);
    __sincosf(0.5f * x1, &s[1], &c[1]);
    __sincosf(0.5f * x2, &s[2], &c[2]);
    __sincosf(0.5f * x3, &s[3], &c[3]);

    float p01[4] = {c[0]*c[1], c[0]*s[1], s[0]*c[1], s[0]*s[1]};
    float p23[4] = {c[2]*c[3], c[2]*s[3], s[2]*c[3], s[2]*s[3]};
    float st[16];
#pragma unroll
    for (int i = 0; i < 16; i++) st[i] = p01[i >> 2] * p23[i & 3];

#pragma unroll
    for (int l = 0; l < 2; l++) {
#pragma unroll
        for (int w = 0; w < 4; w++) {
            float2 v = sTrig[l * 4 + w];
            float cc = v.x, ss = v.y;
            int mask = 8 >> w;
#pragma unroll
            for (int i = 0; i < 16; i++) {
                if (i & mask) continue;
                int j = i | mask;
                float a0 = st[i], a1 = st[j];
                st[i] = cc * a0 - ss * a1;
                st[j] = ss * a0 + cc * a1;
            }
        }
#pragma unroll
        for (int w = 0; w < 4; w++) {
            int cm = 8 >> w;
            int tm = 8 >> ((w + 1) & 3);
#pragma unroll
            for (int i = 0; i < 16; i++) {
                if ((i & cm) && !(i & tm)) {
                    int j = i | tm;
                    float tt = st[i]; st[i] = st[j]; st[j] = tt;
                }
            }
        }
    }

    float q[16];
#pragma unroll
    for (int i = 0; i < 16; i++) q[i] = st[i] * st[i];
#pragma unroll
    for (int w = 0; w < 4; w++) {
        int mask = 8 >> w;
        float z = 0.f;
#pragma unroll
        for (int i = 0; i < 16; i++) z += (i & mask) ? -q[i] : q[i];
        o[w] = z;
    }
}

// ============================== prep kernel ================================
// Split W1[784,128] fp32 -> g_w1h/g_w1l [KP][128] bf16, SAME layout (k-major).
__global__ __launch_bounds__(256) void prep_kernel(const float* __restrict__ W1)
{
    int idx = blockIdx.x * blockDim.x + threadIdx.x;   // 0 .. 25087
    if (idx >= 784 * 32) return;
    float4 v = reinterpret_cast<const float4*>(W1)[idx];
    __nv_bfloat16 h[4], l[4];
    float vv[4] = {v.x, v.y, v.z, v.w};
#pragma unroll
    for (int j = 0; j < 4; j++) {
        h[j] = __float2bfloat16(vv[j]);
        l[j] = __float2bfloat16(vv[j] - __bfloat162float(h[j]));
    }
    reinterpret_cast<uint2*>(g_w1h)[idx] =
        *reinterpret_cast<uint2*>(h);
    reinterpret_cast<uint2*>(g_w1l)[idx] =
        *reinterpret_cast<uint2*>(l);
}

// =============================== fused kernel ==============================
// Grid = B/32 CTAs x 512 thr (2 K-groups of 8 warps). C[32x128].
// A: [row 32][k 32] bf16, ASTR=40 (80B) -> LDSM banks 20r, conflict-free.
// B: [k 32][n 128] bf16, BSTR=136 (272B) -> LDSM banks 4r, conflict-free.
#define ASTR 40
#define BSTR 136
#define A_SLOT 5120                    // Ah(2560) + Al(2560)
#define B_SLOT 17408                   // Bh(8704) + Bl(8704)
#define A_GRP  (3 * A_SLOT)            // 15360
#define B_GRP  (3 * B_SLOT)            // 52224
#define GRP_B  (A_GRP + B_GRP)         // 67584
#define DSMEM_B (2 * GRP_B)            // 135168
#define CSTR 132

__global__ __launch_bounds__(512, 1) void fused_kernel(
    const float* __restrict__ x, const float* __restrict__ theta,
    const __nv_bfloat16* __restrict__ wh, const __nv_bfloat16* __restrict__ wl,
    const float* __restrict__ b1, const float* __restrict__ W2,
    const float* __restrict__ b2, float* __restrict__ out, int B)
{
    extern __shared__ __align__(16) char db[];
    __shared__ float2 sTrig[8];
    __shared__ float sW2t[1280];      // [q][128]
    __shared__ float sb1[128];

    int tid = threadIdx.x;
    int wid = tid >> 5;
    int lane = tid & 31;
    int g = wid >> 3;                 // K group 0/1
    int gw = wid & 7;
    int gtid = tid & 255;
    int row0 = blockIdx.x * 32;

    if (tid < 8) {
        float c, s;
        __sincosf(0.5f * __ldg(&theta[tid]), &s, &c);
        sTrig[tid] = make_float2(c, s);
    }
    for (int i = tid; i < 1280; i += 512) {
        int qq = i >> 7, n = i & 127;
        sW2t[i] = W2[n * 10 + qq];
    }
    if (tid < 128) sb1[tid] = b1[tid];
    __syncthreads();

    char* gb = db + g * GRP_B;
    uint32_t gbs = smem_u32(db) + g * GRP_B;

    // thread roles within group
    int row = gtid >> 3;              // 0..31  (batch row within tile)
    int pl  = gtid & 7;               // patch-in-chunk / B column-granule
    int img = row0 + row;
    const uint4* wh4 = reinterpret_cast<const uint4*>(wh);
    const uint4* wl4 = reinterpret_cast<const uint4*>(wl);

    // ---- x prefetch (chunk c -> xr[c&1]) ----
    float4 xr[2];
    auto loadx = [&](int ci, float4& dst) {
        int patch = (g * HCHK + ci) * 8 + pl;
        if (patch < 196 && img < B) {
            int r14 = patch / 14, c14 = patch - r14 * 14;
            const float* xb = x + (size_t)img * 784 + r14 * 56 + c14 * 2;
            float2 a = *reinterpret_cast<const float2*>(xb);
            float2 b = *reinterpret_cast<const float2*>(xb + 28);
            dst = make_float4(a.x, a.y, b.x, b.y);
        } else {
            dst = make_float4(0.f, 0.f, 0.f, 0.f);
        }
    };

    // ---- circuit -> A slot (STS) ----
    auto circuit_sts = [&](int ci, const float4& xv, int slot) {
        int patch = (g * HCHK + ci) * 8 + pl;
        uint32_t h01 = 0, h23 = 0, l01 = 0, l23 = 0;
        if (patch < 196 && img < B) {
            float o[4];
            run_circuit(xv.x, xv.y, xv.z, xv.w, sTrig, o);
            __nv_bfloat16 h[4], l[4];
#pragma unroll
            for (int w = 0; w < 4; w++) {
                h[w] = __float2bfloat16(o[w]);
                l[w] = __float2bfloat16(o[w] - __bfloat162float(h[w]));
            }
            h01 = *reinterpret_cast<uint32_t*>(h);
            h23 = *reinterpret_cast<uint32_t*>(h + 2);
            l01 = *reinterpret_cast<uint32_t*>(l);
            l23 = *reinterpret_cast<uint32_t*>(l + 2);
        }
        uint32_t off = slot * A_SLOT + row * 80 + pl * 8;
        *reinterpret_cast<uint2*>(gb + off)        = make_uint2(h01, h23);
        *reinterpret_cast<uint2*>(gb + off + 2560) = make_uint2(l01, l23);
    };

    // ---- B staging (cp.async): chunk rows k-major, 16 granules of 16B/row --
    auto issueB = [&](int ci, int slot) {
        int kglob = (g * HCHK + ci) * 32;
        size_t srow = (size_t)(kglob + row) * 16;     // 128 bf16 = 16 granules
        uint32_t dbase = gbs + A_GRP + slot * B_SLOT + row * 272;
        cp16(dbase + pl * 16,        wh4 + srow + pl);
        cp16(dbase + (pl + 8) * 16,  wh4 + srow + pl + 8);
        cp16(dbase + 8704 + pl * 16,       wl4 + srow + pl);
        cp16(dbase + 8704 + (pl + 8) * 16, wl4 + srow + pl + 8);
    };

    int mt = gw & 1;
    int nt0 = (gw >> 1) * 2;

    wmma::fragment<wmma::accumulator, 16, 16, 16, float> acc[2];
    wmma::fill_fragment(acc[0], 0.f);
    wmma::fill_fragment(acc[1], 0.f);

    // ---- prologue ----
    loadx(0, xr[0]);
    loadx(1, xr[1]);
    issueB(0, 0); CP_COMMIT();
    issueB(1, 1); CP_COMMIT();
    circuit_sts(0, xr[0], 0);

    // ---- mainloop ----
    for (int i = 0; i < HCHK; i++) {
        if (i + 2 < HCHK) loadx(i + 2, xr[i & 1]);            // for iter i+1
        if (i + 1 < HCHK) circuit_sts(i + 1, xr[(i + 1) & 1], (i + 1) % 3);
        if (i + 2 < HCHK) issueB(i + 2, (i + 2) % 3);
        CP_COMMIT();                                          // 1 commit / iter
        cp_wait<2>();                                         // chunk i ready
        gbar(1 + g);

        const __nv_bfloat16* sAh = reinterpret_cast<const __nv_bfloat16*>(
            gb + (i % 3) * A_SLOT);
        const __nv_bfloat16* sAl = sAh + 1280;                // 2560 B
        const __nv_bfloat16* sBh = reinterpret_cast<const __nv_bfloat16*>(
            gb + A_GRP + (i % 3) * B_SLOT);
        const __nv_bfloat16* sBl = sBh + 4352;                // 8704 B

#pragma unroll
        for (int ks = 0; ks < 2; ks++) {
            wmma::fragment<wmma::matrix_a, 16, 16, 16, __nv_bfloat16, wmma::row_major> ah, al;
            wmma::load_matrix_sync(ah, sAh + mt * 16 * ASTR + ks * 16, ASTR);
            wmma::load_matrix_sync(al, sAl + mt * 16 * ASTR + ks * 16, ASTR);
#pragma unroll
            for (int j = 0; j < 2; j++) {
                wmma::fragment<wmma::matrix_b, 16, 16, 16, __nv_bfloat16, wmma::row_major> bh, bl;
                wmma::load_matrix_sync(bh, sBh + ks * 16 * BSTR + (nt0 + j) * 16, BSTR);
                wmma::load_matrix_sync(bl, sBl + ks * 16 * BSTR + (nt0 + j) * 16, BSTR);
                wmma::mma_sync(acc[j], ah, bh, acc[j]);
                wmma::mma_sync(acc[j], ah, bl, acc[j]);
                wmma::mma_sync(acc[j], al, bh, acc[j]);
            }
        }
    }

    // ---- both groups done before C staging overwrites buffers ----
    __syncthreads();

    float* sC = reinterpret_cast<float*>(db);            // 2 x [32][CSTR]
    float* sCg = sC + g * 32 * CSTR;
    wmma::store_matrix_sync(sCg + mt * 16 * CSTR + nt0 * 16, acc[0], CSTR, wmma::mem_row_major);
    wmma::store_matrix_sync(sCg + mt * 16 * CSTR + (nt0 + 1) * 16, acc[1], CSTR, wmma::mem_row_major);
    __syncthreads();

    // ---- fused bias/relu + 128->10 GEMM + log_softmax (warp per 2 rows) ----
    const float* sC0 = sC;
    const float* sC1 = sC + 32 * CSTR;
#pragma unroll
    for (int rr = 0; rr < 2; rr++) {
        int r = wid * 2 + rr;
        float hv[4];
#pragma unroll
        for (int j = 0; j < 4; j++) {
            int col = lane + 32 * j;
            float h = sC0[r * CSTR + col] + sC1[r * CSTR + col] + sb1[col];
            hv[j] = h > 0.f ? h : 0.f;
        }
        float lg[10];
#pragma unroll
        for (int qq = 0; qq < 10; qq++) lg[qq] = 0.f;
#pragma unroll
        for (int j = 0; j < 4; j++)
#pragma unroll
            for (int qq = 0; qq < 10; qq++)
                lg[qq] = fmaf(hv[j], sW2t[qq * 128 + lane + 32 * j], lg[qq]);
#pragma unroll
        for (int off = 16; off; off >>= 1)
#pragma unroll
            for (int qq = 0; qq < 10; qq++)
                lg[qq] += __shfl_xor_sync(0xffffffffu, lg[qq], off);

        if (lane == 0) {
            int orow = row0 + r;
            if (orow < B) {
                float lv[10];
                float m = -1e30f;
#pragma unroll
                for (int qq = 0; qq < 10; qq++) {
                    lv[qq] = lg[qq] + __ldg(&b2[qq]);
                    m = fmaxf(m, lv[qq]);
                }
                float se = 0.f;
#pragma unroll
                for (int qq = 0; qq < 10; qq++) se += expf(lv[qq] - m);
                float lse = m + logf(se);
#pragma unroll
                for (int qq = 0; qq < 10; qq++)
                    out[(size_t)orow * 10 + qq] = lv[qq] - lse;
            }
        }
    }
}

// ================================ launch ===================================
extern "C" void kernel_launch(void* const* d_in, const int* in_sizes, int n_in,
                              void* d_out, int out_size) {
    const float* x     = (const float*)d_in[0];   // [B, 784]
    const float* theta = (const float*)d_in[1];   // [2, 4]
    const float* W1    = (const float*)d_in[2];   // [784, 128]
    const float* b1    = (const float*)d_in[3];   // [128]
    const float* W2    = (const float*)d_in[4];   // [128, 10]
    const float* b2    = (const float*)d_in[5];   // [10]
    float* out = (float*)d_out;

    int B = in_sizes[0] / 784;
    if (B > MAX_B) B = MAX_B;

    __nv_bfloat16 *wh, *wl;
    cudaGetSymbolAddress((void**)&wh, g_w1h);
    cudaGetSymbolAddress((void**)&wl, g_w1l);

    cudaFuncSetAttribute(fused_kernel,
                         cudaFuncAttributeMaxDynamicSharedMemorySize, DSMEM_B);

    prep_kernel<<<98, 256>>>(W1);

    int mtiles = (B + 31) / 32;
    fused_kernel<<<mtiles, 512, DSMEM_B>>>(x, theta, wh, wl, b1, W2, b2, out, B);
}